// round 7
// baseline (speedup 1.0000x reference)
#include <cuda_runtime.h>

#define G 34
#define NPX 1156            // 34*34
#define CH_STRIDE 1160      // padded channel stride in smem
#define NTHREADS 256

typedef unsigned long long ull;

struct SmemLayout {
    ull   wfc1[64 * 12];    // fc1_w duplicated-packed (w,w), layout [o][k]
    ull   wfc2[64 * 4];     // fc2_w duplicated-packed, layout [o][c]
    ull   bfc1[64];
    ull   bfc2[4];
    float bufA[4 * CH_STRIDE];
    float bufB[4 * CH_STRIDE];
    float scent[NPX];
    int   hist[256];
    unsigned char mask[NPX];
    int   s_cl, s_z, s_ones, s_selbin, s_want;
    float s_red[NTHREADS / 32];
    int   s_redi[NTHREADS / 32];
};

__device__ __forceinline__ ull pack2(float lo, float hi) {
    ull d; asm("mov.b64 %0, {%1,%2};" : "=l"(d) : "f"(lo), "f"(hi)); return d;
}
__device__ __forceinline__ void unpack2(ull d, float& lo, float& hi) {
    asm("mov.b64 {%0,%1}, %2;" : "=f"(lo), "=f"(hi) : "l"(d));
}
__device__ __forceinline__ ull fma2(ull a, ull b, ull c) {
    ull d; asm("fma.rn.f32x2 %0, %1, %2, %3;" : "=l"(d) : "l"(a), "l"(b), "l"(c)); return d;
}

// 3x3 max over valid neighbors (equivalent to -inf padded maxpool)
__device__ __forceinline__ float mp3(const float* __restrict__ ch, int r, int c) {
    float m = -1e30f;
    #pragma unroll
    for (int dr = -1; dr <= 1; ++dr) {
        int rr = r + dr;
        if (rr < 0 || rr >= G) continue;
        #pragma unroll
        for (int dc = -1; dc <= 1; ++dc) {
            int cc = c + dc;
            if (cc < 0 || cc >= G) continue;
            m = fmaxf(m, ch[rr * G + cc]);
        }
    }
    return m;
}

__global__ void __launch_bounds__(NTHREADS)
ca_kernel(const float* __restrict__ g_cell, const float* __restrict__ g_food,
          const float* __restrict__ g_fc1w, const float* __restrict__ g_fc1b,
          const float* __restrict__ g_fc2w, const float* __restrict__ g_fc2b,
          const float* __restrict__ g_sk, const int* __restrict__ g_steps,
          float* __restrict__ g_out, int B)
{
    extern __shared__ unsigned char dynraw[];
    SmemLayout& sm = *reinterpret_cast<SmemLayout*>(dynraw);
    const int b    = blockIdx.x;
    const int tid  = threadIdx.x;
    const int lane = tid & 31;
    const int wid  = tid >> 5;

    int steps = 32;
    if (g_steps) {
        int s = g_steps[0];
        if (s >= 0 && s <= 100000) steps = s;
    }

    // ---- stage weights (duplicated-packed pairs) ----
    for (int i = tid; i < 64 * 12; i += NTHREADS) { float w = g_fc1w[i]; sm.wfc1[i] = pack2(w, w); }
    for (int i = tid; i < 256; i += NTHREADS) {
        int c = i >> 6, o = i & 63;
        float w = g_fc2w[i];                 // fc2_w is [4][64]
        sm.wfc2[o * 4 + c] = pack2(w, w);    // transpose to [o][c]
    }
    for (int i = tid; i < 64; i += NTHREADS) { float w = g_fc1b[i]; sm.bfc1[i] = pack2(w, w); }
    if (tid < 4) { float w = g_fc2b[tid]; sm.bfc2[tid] = pack2(w, w); }

    // ---- stage food + scent kernel into bufB (free until first step's phase B) ----
    float* f_s = sm.bufB;
    float* k_s = sm.bufB + 1280;
    for (int i = tid; i < NPX; i += NTHREADS) f_s[i] = g_food[(size_t)b * NPX + i];
    for (int i = tid; i < 361; i += NTHREADS) k_s[i] = g_sk[i];
    // ---- load cell state ----
    for (int i = tid; i < 4 * NPX; i += NTHREADS) {
        int c = i / NPX, p = i - c * NPX;
        sm.bufA[c * CH_STRIDE + p] = g_cell[(size_t)b * 4 * NPX + i];
    }
    __syncthreads();

    // ---- scent = conv19x19(food, kernel), pad 9, zero padding ----
    for (int i = tid; i < NPX; i += NTHREADS) {
        int r = i / G, c = i - r * G;
        float acc = 0.f;
        int u0 = (r - 9 < 0) ? 0 : r - 9, u1 = (r + 9 > G - 1) ? G - 1 : r + 9;
        int v0 = (c - 9 < 0) ? 0 : c - 9, v1 = (c + 9 > G - 1) ? G - 1 : c + 9;
        for (int u = u0; u <= u1; ++u) {
            const float* fr = f_s + u * G;
            const float* kr = k_s + (u - r + 9) * 19 + (9 - c);
            for (int v = v0; v <= v1; ++v) acc += fr[v] * kr[v];
        }
        sm.scent[i] = acc;
    }
    __syncthreads();

    float* cur = sm.bufA;
    float* nxt = sm.bufB;

    for (int s = 0; s < steps; ++s) {
        // ---- Phase A: set ch3 = scent, count cl = #(ch0 > 0.8), pre_mask ----
        if (tid == 0) { sm.s_cl = 0; sm.s_z = 0; sm.s_ones = 0; }
        __syncthreads();
        {
            float* c0 = cur;
            float* c3 = cur + 3 * CH_STRIDE;
            int lcl = 0;
            for (int i = tid; i < NPX; i += NTHREADS) {
                c3[i] = sm.scent[i];
                int r = i / G, c = i - r * G;
                float v0 = c0[i];
                lcl += (v0 > 0.8f) ? 1 : 0;
                float m = mp3(c0, r, c);
                sm.mask[i] = (m > 0.1f) ? 1 : 0;
            }
            atomicAdd(&sm.s_cl, lcl);
        }
        __syncthreads();

        // ---- Phase B: sobel + MLP per pixel-PAIR (packed f32x2) ----
        for (int p = tid; p < NPX / 2; p += NTHREADS) {
            int p2 = 2 * p;
            int r = p2 / G, c0i = p2 - r * G;   // c0i is even; pair never crosses a row
            ull yv[12];
            #pragma unroll
            for (int ch = 0; ch < 4; ++ch) {
                const float* C = cur + ch * CH_STRIDE;
                float nn[12];
                #pragma unroll
                for (int dr = 0; dr < 3; ++dr) {
                    int rr = r + dr - 1;
                    #pragma unroll
                    for (int dc = 0; dc < 4; ++dc) {
                        int cc = c0i + dc - 1;
                        nn[dr * 4 + dc] = (rr >= 0 && rr < G && cc >= 0 && cc < G)
                                              ? C[rr * G + cc] : 0.f;
                    }
                }
                // sobel-x: rows weighted [1,2,1], cols [-1,0,1], /8 (exact pow2 scales)
                float y1L = ((nn[2]  - nn[0]) + 2.f * (nn[6]  - nn[4]) + (nn[10] - nn[8])) * 0.125f;
                float y1R = ((nn[3]  - nn[1]) + 2.f * (nn[7]  - nn[5]) + (nn[11] - nn[9])) * 0.125f;
                // sobel-y = transpose
                float y2L = ((nn[8]  - nn[0]) + 2.f * (nn[9]  - nn[1]) + (nn[10] - nn[2])) * 0.125f;
                float y2R = ((nn[9]  - nn[1]) + 2.f * (nn[10] - nn[2]) + (nn[11] - nn[3])) * 0.125f;
                yv[ch]     = pack2(nn[5], nn[6]);   // cell values (centers)
                yv[4 + ch] = pack2(y1L, y1R);
                yv[8 + ch] = pack2(y2L, y2R);
            }
            ull u0 = sm.bfc2[0], u1 = sm.bfc2[1], u2 = sm.bfc2[2], u3 = sm.bfc2[3];
            #pragma unroll 8
            for (int o = 0; o < 64; ++o) {
                ull h = sm.bfc1[o];
                const ulonglong2* w = reinterpret_cast<const ulonglong2*>(sm.wfc1 + o * 12);
                #pragma unroll
                for (int kk = 0; kk < 6; ++kk) {
                    ulonglong2 ww = w[kk];
                    h = fma2(yv[2 * kk],     ww.x, h);
                    h = fma2(yv[2 * kk + 1], ww.y, h);
                }
                float hl, hh; unpack2(h, hl, hh);
                h = pack2(fmaxf(hl, 0.f), fmaxf(hh, 0.f));     // relu
                const ulonglong2* w2 = reinterpret_cast<const ulonglong2*>(sm.wfc2 + o * 4);
                ulonglong2 wa = w2[0], wb = w2[1];
                u0 = fma2(h, wa.x, u0);
                u1 = fma2(h, wa.y, u1);
                u2 = fma2(h, wb.x, u2);
                u3 = fma2(h, wb.y, u3);
            }
            float cl_, cr_, ul, ur;
            unpack2(yv[0], cl_, cr_); unpack2(u0, ul, ur);
            nxt[p2] = cl_ + ul;                         nxt[p2 + 1] = cr_ + ur;
            unpack2(yv[1], cl_, cr_); unpack2(u1, ul, ur);
            nxt[CH_STRIDE + p2] = cl_ + ul;             nxt[CH_STRIDE + p2 + 1] = cr_ + ur;
            unpack2(yv[2], cl_, cr_); unpack2(u2, ul, ur);
            nxt[2 * CH_STRIDE + p2] = cl_ + ul;         nxt[2 * CH_STRIDE + p2 + 1] = cr_ + ur;
            unpack2(yv[3], cl_, cr_); unpack2(u3, ul, ur);
            nxt[3 * CH_STRIDE + p2] = cl_ + ul;         nxt[3 * CH_STRIDE + p2 + 1] = cr_ + ur;
        }
        __syncthreads();

        // ---- Phase C1: mask = pre_mask && (maxpool3(x0_raw) > 0.1) ----
        for (int i = tid; i < NPX; i += NTHREADS) {
            int r = i / G, c = i - r * G;
            float m = mp3(nxt, r, c);
            sm.mask[i] = (sm.mask[i] && (m > 0.1f)) ? 1 : 0;
        }
        __syncthreads();

        // ---- Phase C2: apply mask, clip, count exact zeros/ones on ch0 ----
        {
            int lz = 0, lo = 0;
            for (int i = tid; i < NPX; i += NTHREADS) {
                bool m = sm.mask[i] != 0;
                float v0f = 0.f;
                #pragma unroll
                for (int c = 0; c < 4; ++c) {
                    float v = m ? nxt[c * CH_STRIDE + i] : 0.f;
                    v = fminf(fmaxf(v, -10.f), 10.f);
                    if (c == 0) { v = fminf(fmaxf(v, 0.f), 1.f); v0f = v; }
                    nxt[c * CH_STRIDE + i] = v;
                }
                lz += (v0f == 0.f) ? 1 : 0;
                lo += (v0f == 1.f) ? 1 : 0;
            }
            atomicAdd(&sm.s_z, lz);
            atomicAdd(&sm.s_ones, lo);
        }
        __syncthreads();

        // ---- Selection: kth = sorted_ascending[min(cl,1155)], exact ----
        int want = sm.s_cl; if (want > NPX - 1) want = NPX - 1;
        const int nz = sm.s_z, no = sm.s_ones;
        float kth;
        if (want < nz) {
            kth = 0.f;
        } else if (want >= NPX - no) {
            kth = 1.0f;
        } else {
            want -= nz;                        // rank among interior (0,1) values
            unsigned int prefix = 0;
            for (int pass = 0; pass < 4; ++pass) {
                int shift = 24 - 8 * pass;
                for (int bb = tid; bb < 256; bb += NTHREADS) sm.hist[bb] = 0;
                __syncthreads();
                for (int i = tid; i < NPX; i += NTHREADS) {
                    float v = nxt[i];
                    if (v > 0.f && v < 1.f) {
                        unsigned int bits = __float_as_uint(v);
                        bool ok = (pass == 0) || ((bits >> (shift + 8)) == prefix);
                        if (ok) atomicAdd(&sm.hist[(bits >> shift) & 255], 1);
                    }
                }
                __syncthreads();
                if (tid < 32) {
                    int h[8]; int ssum = 0;
                    #pragma unroll
                    for (int j = 0; j < 8; ++j) { h[j] = sm.hist[tid * 8 + j]; ssum += h[j]; }
                    int inc = ssum;
                    #pragma unroll
                    for (int off = 1; off < 32; off <<= 1) {
                        int t = __shfl_up_sync(0xffffffffu, inc, off);
                        if (lane >= off) inc += t;
                    }
                    int excl = inc - ssum;
                    if (want >= excl && want < excl + ssum) {
                        int w = want - excl;
                        int bsel = 0;
                        while (w >= h[bsel]) { w -= h[bsel]; ++bsel; }
                        sm.s_selbin = tid * 8 + bsel;
                        sm.s_want   = w;
                    }
                }
                __syncthreads();
                prefix = (prefix << 8) | (unsigned int)sm.s_selbin;
                want = sm.s_want;
            }
            kth = __uint_as_float(prefix);
        }

        // ---- Phase D: keep only ch0 values strictly > kth ----
        for (int i = tid; i < NPX; i += NTHREADS) {
            float v = nxt[i];
            if (!(v > kth)) nxt[i] = 0.f;
        }
        __syncthreads();

        float* t = cur; cur = nxt; nxt = t;   // ping-pong
    }

    // ---- outputs: [cell | food | total_pixel_val | living_count] ----
    float* fin = cur;
    const size_t outCell = (size_t)b * 4 * NPX;
    for (int i = tid; i < 4 * NPX; i += NTHREADS) {
        int c = i / NPX, p = i - c * NPX;
        g_out[outCell + i] = fin[c * CH_STRIDE + p];
    }
    const size_t foodBase = (size_t)B * 4 * NPX;
    for (int i = tid; i < NPX; i += NTHREADS)
        g_out[foodBase + (size_t)b * NPX + i] = g_food[(size_t)b * NPX + i];

    float lt = 0.f; int lv = 0;
    for (int i = tid; i < NPX; i += NTHREADS) {
        float v = fin[i];
        lt += v;
        lv += (v > 0.1f) ? 1 : 0;
    }
    #pragma unroll
    for (int off = 16; off; off >>= 1) {
        lt += __shfl_down_sync(0xffffffffu, lt, off);
        lv += __shfl_down_sync(0xffffffffu, lv, off);
    }
    if (lane == 0) { sm.s_red[wid] = lt; sm.s_redi[wid] = lv; }
    __syncthreads();
    if (tid == 0) {
        float T = 0.f; int L = 0;
        #pragma unroll
        for (int w = 0; w < NTHREADS / 32; ++w) { T += sm.s_red[w]; L += sm.s_redi[w]; }
        size_t tBase = foodBase + (size_t)B * NPX;
        g_out[tBase + b]     = T;
        g_out[tBase + B + b] = (float)L;
    }
}

extern "C" void kernel_launch(void* const* d_in, const int* in_sizes, int n_in,
                              void* d_out, int out_size) {
    (void)out_size;
    const float* cell  = (const float*)d_in[0];
    const float* food  = (const float*)d_in[1];
    const float* fc1w  = (const float*)d_in[2];
    const float* fc1b  = (const float*)d_in[3];
    const float* fc2w  = (const float*)d_in[4];
    const float* fc2b  = (const float*)d_in[5];
    const float* sk    = (const float*)d_in[6];
    const int*   steps = (n_in >= 8) ? (const int*)d_in[7] : nullptr;

    int B = in_sizes[0] / (4 * NPX);
    size_t smem = sizeof(SmemLayout);
    cudaFuncSetAttribute(ca_kernel, cudaFuncAttributeMaxDynamicSharedMemorySize, (int)smem);
    ca_kernel<<<B, NTHREADS, smem>>>(cell, food, fc1w, fc1b, fc2w, fc2b, sk, steps,
                                     (float*)d_out, B);
}